// round 5
// baseline (speedup 1.0000x reference)
#include <cuda_runtime.h>
#include <cuda_fp16.h>
#include <math.h>

// Problem constants
#define B   64
#define T   100
#define S   1024
#define IN  256
#define TRG 512
#define ENC 512
#define G4  2048   // 4*TRG

// Output layout offsets (floats)
#define OUT_OFF   0
#define HT_OFF    3276800
#define CT_OFF    3309568
#define HAT_OFF   3342336
#define ATTN_OFF  3375104
#define PAT_OFF   9928704
#define PGEN_OFF  9994240
#define PDH_OFF   10000640
#define LOSS_OFF  10033408

// ---------------- device state ----------------
__device__ __align__(16) __half  g_encproj_h[(size_t)B * S * TRG];   // 67 MB
__device__ __align__(16) __half  g_enc_h[(size_t)B * S * ENC];       // 67 MB
__device__ __align__(16) __half  g_wen_h[512 * 512];
__device__ __align__(16) __half  g_input_h[B * T * IN];
__device__ __align__(16) __half  g_wihx_h[G4 * IN];
__device__ __align__(16) float   g_xg[(size_t)B * T * G4];           // 52 MB
__device__ __align__(16) float g_h[2][B * TRG];
__device__ __align__(16) float g_c[2][B * TRG];
__device__ __align__(16) float g_ha[2][B * TRG];
__device__ __align__(16) float g_pa[2][B * S];
__device__ __align__(16) float g_hde[B * TRG];
__device__ __align__(16) float g_attn[B * S];
__device__ __align__(16) float g_cenc[B * TRG];

__device__ __forceinline__ float warp_red_sum(float v) {
#pragma unroll
    for (int o = 16; o; o >>= 1) v += __shfl_xor_sync(0xffffffffu, v, o);
    return v;
}
__device__ __forceinline__ float sigmoidf_(float x) { return 1.0f / (1.0f + expf(-x)); }
__device__ __forceinline__ float tanh_ap(float x) {
    float y; asm("tanh.approx.f32 %0, %1;" : "=f"(y) : "f"(x)); return y;
}
__device__ __forceinline__ unsigned smem_u32(const void* p) {
    return (unsigned)__cvta_generic_to_shared(p);
}

// ---------------- init ----------------
__global__ void k_init(const float* __restrict__ h0, const float* __restrict__ c0,
                       const float* __restrict__ h_attn, const float* __restrict__ past_attn) {
    int i = blockIdx.x * blockDim.x + threadIdx.x;
    if (i < B * TRG) { g_h[0][i] = h0[i]; g_c[0][i] = c0[i]; g_ha[0][i] = h_attn[i]; }
    if (i < B * S) g_pa[0][i] = past_attn[i];
}

// ---------------- generic f32 -> f16 ----------------
__global__ void k_f2h(const float* __restrict__ src, __half* __restrict__ dst) {
    size_t i = ((size_t)blockIdx.x * blockDim.x + threadIdx.x) * 4;
    float4 v = *(const float4*)&src[i];
    __half2* d = (__half2*)&dst[i];
    d[0] = __floats2half2_rn(v.x, v.y);
    d[1] = __floats2half2_rn(v.z, v.w);
}

// w_ih[:, 0:256] (row stride 768) -> compact fp16 [2048][256]
__global__ void k_wihx(const float* __restrict__ w_ih) {
    int n = blockIdx.x;
    for (int c = threadIdx.x; c < IN; c += 64)
        g_wihx_h[n * IN + c] = __float2half_rn(w_ih[(size_t)n * (IN + TRG) + c]);
}

// ---------------- fp16 tensor-core GEMM (setup only) ----------------
template<bool OUT16>
__global__ void k_mma(const __half* __restrict__ A, const __half* __restrict__ W,
                      const float* __restrict__ bias, void* __restrict__ Cout,
                      int K, int ldc) {
    __shared__ __align__(16) char smem_raw[128 * 68 * 4];  // 34816 B
    __shared__ float sBias[64];
    __half (*sA)[72] = (__half(*)[72])smem_raw;
    __half (*sB)[72] = (__half(*)[72])(smem_raw + 18432);

    const int m0 = blockIdx.y * 128;
    const int n0 = blockIdx.x * 64;
    const int tid = threadIdx.x;
    const int lane = tid & 31;
    const int w = tid >> 5;
    const int wm = (w >> 1) * 32;
    const int wn = (w & 1) * 32;

    if (OUT16 && tid < 64) sBias[tid] = bias[n0 + tid];

    float c[2][4][4];
#pragma unroll
    for (int i = 0; i < 2; i++)
#pragma unroll
        for (int j = 0; j < 4; j++)
#pragma unroll
            for (int q = 0; q < 4; q++) c[i][j][q] = 0.f;

    const int lrow = lane & 15;
    const int lcol = (lane >> 4) * 8;

    for (int k0 = 0; k0 < K; k0 += 64) {
        __syncthreads();
        {
            int r = tid >> 3, cc = (tid & 7) * 8;
#pragma unroll
            for (int p = 0; p < 4; p++)
                *(float4*)&sA[r + p * 32][cc] =
                    *(const float4*)&A[(size_t)(m0 + r + p * 32) * K + k0 + cc];
#pragma unroll
            for (int p = 0; p < 2; p++)
                *(float4*)&sB[r + p * 32][cc] =
                    *(const float4*)&W[(size_t)(n0 + r + p * 32) * K + k0 + cc];
        }
        __syncthreads();
#pragma unroll
        for (int kk = 0; kk < 4; kk++) {
            unsigned a[2][4], bf[4][2];
#pragma unroll
            for (int mt = 0; mt < 2; mt++) {
                unsigned addr = smem_u32(&sA[wm + mt * 16 + lrow][kk * 16 + lcol]);
                asm volatile("ldmatrix.sync.aligned.m8n8.x4.shared.b16 {%0,%1,%2,%3}, [%4];"
                             : "=r"(a[mt][0]), "=r"(a[mt][1]), "=r"(a[mt][2]), "=r"(a[mt][3])
                             : "r"(addr));
            }
#pragma unroll
            for (int bp = 0; bp < 2; bp++) {
                unsigned r0, r1, r2, r3;
                unsigned addr = smem_u32(&sB[wn + bp * 16 + lrow][kk * 16 + lcol]);
                asm volatile("ldmatrix.sync.aligned.m8n8.x4.shared.b16 {%0,%1,%2,%3}, [%4];"
                             : "=r"(r0), "=r"(r1), "=r"(r2), "=r"(r3) : "r"(addr));
                bf[bp * 2 + 0][0] = r0; bf[bp * 2 + 0][1] = r2;
                bf[bp * 2 + 1][0] = r1; bf[bp * 2 + 1][1] = r3;
            }
#pragma unroll
            for (int mt = 0; mt < 2; mt++)
#pragma unroll
                for (int nf = 0; nf < 4; nf++) {
                    asm volatile(
                        "mma.sync.aligned.m16n8k16.row.col.f32.f16.f16.f32 "
                        "{%0,%1,%2,%3}, {%4,%5,%6,%7}, {%8,%9}, {%0,%1,%2,%3};"
                        : "+f"(c[mt][nf][0]), "+f"(c[mt][nf][1]),
                          "+f"(c[mt][nf][2]), "+f"(c[mt][nf][3])
                        : "r"(a[mt][0]), "r"(a[mt][1]), "r"(a[mt][2]), "r"(a[mt][3]),
                          "r"(bf[nf][0]), "r"(bf[nf][1]));
                }
        }
    }
    __syncthreads();
    float (*sO)[68] = (float(*)[68])smem_raw;
    {
        int g = lane >> 2, tq = lane & 3;
#pragma unroll
        for (int mt = 0; mt < 2; mt++)
#pragma unroll
            for (int nf = 0; nf < 4; nf++) {
                int r = wm + mt * 16 + g;
                int cc = wn + (nf >> 1) * 16 + (nf & 1) * 8 + tq * 2;
                sO[r][cc]     = c[mt][nf][0]; sO[r][cc + 1]     = c[mt][nf][1];
                sO[r + 8][cc] = c[mt][nf][2]; sO[r + 8][cc + 1] = c[mt][nf][3];
            }
    }
    __syncthreads();
#pragma unroll
    for (int p = 0; p < 4; p++) {
        int idx = p * 256 + tid;
        int r = idx >> 3, c8 = (idx & 7) * 8;
        if (OUT16) {
            __half* C = (__half*)Cout;
            __half2 h[4];
#pragma unroll
            for (int q = 0; q < 4; q++)
                h[q] = __floats2half2_rn(sO[r][c8 + 2 * q] + sBias[c8 + 2 * q],
                                         sO[r][c8 + 2 * q + 1] + sBias[c8 + 2 * q + 1]);
            *(float4*)&C[(size_t)(m0 + r) * ldc + n0 + c8] = *(float4*)h;
        } else {
            float* C = (float*)Cout;
            *(float4*)&C[(size_t)(m0 + r) * ldc + n0 + c8]     = *(float4*)&sO[r][c8];
            *(float4*)&C[(size_t)(m0 + r) * ldc + n0 + c8 + 4] = *(float4*)&sO[r][c8 + 4];
        }
    }
}

// ---------------- K1: gates GEMM (full-K) + LSTM pointwise fused ----------------
// grid 64, block 256. Block covers all 64 b x 32 gate-cols:
// col c in [0,32): n = (c>>3)*512 + j0 + (c&7), j0 = blockIdx.x*8
__global__ void k_gates_lstm(const float* __restrict__ w_ih, const float* __restrict__ w_hh,
                             const float* __restrict__ b_ih, const float* __restrict__ b_hh,
                             int cur, int t) {
    __shared__ float As[16][68];
    __shared__ float Bs[16][36];
    __shared__ float sG[64][33];
    const int j0 = blockIdx.x * 8;
    const int tid = threadIdx.x;
    const int ty = tid >> 4, tx = tid & 15;
    const int nxt = cur ^ 1;

    float acc[4][2];
#pragma unroll
    for (int i = 0; i < 4; i++) { acc[i][0] = 0.f; acc[i][1] = 0.f; }

    for (int k0 = 0; k0 < 1024; k0 += 16) {
        __syncthreads();
        // A: X[b][k0..k0+15], X = [ha | h]
        {
            int b = tid >> 2, c4 = (tid & 3) * 4;
            int k = k0 + c4;
            float4 av = (k < TRG) ? *(const float4*)&g_ha[cur][b * TRG + k]
                                  : *(const float4*)&g_h[cur][b * TRG + k - TRG];
            As[c4 + 0][b] = av.x; As[c4 + 1][b] = av.y;
            As[c4 + 2][b] = av.z; As[c4 + 3][b] = av.w;
        }
        // B: Wr[n][k0..k0+15], 32 cols -> 128 float4 slots
        if (tid < 128) {
            int c = tid >> 2, c4 = (tid & 3) * 4;
            int n = (c >> 3) * 512 + j0 + (c & 7);
            int k = k0 + c4;
            float4 bv = (k < TRG) ? *(const float4*)&w_ih[(size_t)n * (IN + TRG) + IN + k]
                                  : *(const float4*)&w_hh[(size_t)n * TRG + k - TRG];
            Bs[c4 + 0][c] = bv.x; Bs[c4 + 1][c] = bv.y;
            Bs[c4 + 2][c] = bv.z; Bs[c4 + 3][c] = bv.w;
        }
        __syncthreads();
#pragma unroll
        for (int kk = 0; kk < 16; kk++) {
            float a[4], bb[2];
#pragma unroll
            for (int i = 0; i < 4; i++) a[i] = As[kk][ty + 16 * i];
            bb[0] = Bs[kk][tx]; bb[1] = Bs[kk][tx + 16];
#pragma unroll
            for (int i = 0; i < 4; i++) {
                acc[i][0] = fmaf(a[i], bb[0], acc[i][0]);
                acc[i][1] = fmaf(a[i], bb[1], acc[i][1]);
            }
        }
    }
    __syncthreads();
#pragma unroll
    for (int i = 0; i < 4; i++) {
        sG[ty + 16 * i][tx]      = acc[i][0];
        sG[ty + 16 * i][tx + 16] = acc[i][1];
    }
    __syncthreads();
    // LSTM pointwise: 512 (b, jj) pairs, 2 per thread
#pragma unroll
    for (int p = 0; p < 2; p++) {
        int idx = tid + p * 256;
        int b = idx >> 3, jj = idx & 7;
        int j = j0 + jj;
        const float* xgp = g_xg + ((size_t)b * T + t) * G4;
        float gi = sG[b][jj]      + b_ih[j]           + b_hh[j]           + xgp[j];
        float gf = sG[b][8 + jj]  + b_ih[TRG + j]     + b_hh[TRG + j]     + xgp[TRG + j];
        float gg = sG[b][16 + jj] + b_ih[2 * TRG + j] + b_hh[2 * TRG + j] + xgp[2 * TRG + j];
        float go = sG[b][24 + jj] + b_ih[3 * TRG + j] + b_hh[3 * TRG + j] + xgp[3 * TRG + j];
        float cn = sigmoidf_(gf) * g_c[cur][b * TRG + j] + sigmoidf_(gi) * tanhf(gg);
        float hn = sigmoidf_(go) * tanhf(cn);
        g_c[nxt][b * TRG + j] = cn;
        g_h[nxt][b * TRG + j] = hn;
    }
}

// ---------------- K2: hde = h_new @ w_de^T as GEMM (w_de read once) ----------------
// grid 16, block 256. Tile: 64 b x 32 j, K=512
__global__ void k_hde(const float* __restrict__ w_de, int cur) {
    __shared__ float As[16][68];
    __shared__ float Bs[16][36];
    const int j0 = blockIdx.x * 32;
    const int tid = threadIdx.x;
    const int ty = tid >> 4, tx = tid & 15;
    const int nxt = cur ^ 1;

    float acc[4][2];
#pragma unroll
    for (int i = 0; i < 4; i++) { acc[i][0] = 0.f; acc[i][1] = 0.f; }

    for (int k0 = 0; k0 < 512; k0 += 16) {
        __syncthreads();
        {
            int b = tid >> 2, c4 = (tid & 3) * 4;
            float4 av = *(const float4*)&g_h[nxt][b * TRG + k0 + c4];
            As[c4 + 0][b] = av.x; As[c4 + 1][b] = av.y;
            As[c4 + 2][b] = av.z; As[c4 + 3][b] = av.w;
        }
        if (tid < 128) {
            int c = tid >> 2, c4 = (tid & 3) * 4;
            float4 bv = *(const float4*)&w_de[(size_t)(j0 + c) * TRG + k0 + c4];
            Bs[c4 + 0][c] = bv.x; Bs[c4 + 1][c] = bv.y;
            Bs[c4 + 2][c] = bv.z; Bs[c4 + 3][c] = bv.w;
        }
        __syncthreads();
#pragma unroll
        for (int kk = 0; kk < 16; kk++) {
            float a[4], bb[2];
#pragma unroll
            for (int i = 0; i < 4; i++) a[i] = As[kk][ty + 16 * i];
            bb[0] = Bs[kk][tx]; bb[1] = Bs[kk][tx + 16];
#pragma unroll
            for (int i = 0; i < 4; i++) {
                acc[i][0] = fmaf(a[i], bb[0], acc[i][0]);
                acc[i][1] = fmaf(a[i], bb[1], acc[i][1]);
            }
        }
    }
#pragma unroll
    for (int i = 0; i < 4; i++) {
        int b = ty + 16 * i;
        g_hde[b * TRG + j0 + tx]      = acc[i][0];
        g_hde[b * TRG + j0 + tx + 16] = acc[i][1];
    }
}

// ---------------- K3: attn_ee logits; warp handles 8 s ----------------
// grid (16, 64), block 256
__global__ void k_attnee(const float* __restrict__ cv_w, const float* __restrict__ warp_w, int cur) {
    __shared__ __align__(16) float sh_hde[TRG], sh_cv[TRG], sh_w[TRG];
    const int b = blockIdx.y, tid = threadIdx.x;
    for (int i = tid; i < TRG; i += 256) {
        sh_hde[i] = g_hde[b * TRG + i];
        sh_cv[i]  = cv_w[i];
        sh_w[i]   = warp_w[i];
    }
    __syncthreads();
    const int warp = tid >> 5, lane = tid & 31;
    const float2* hd2 = (const float2*)sh_hde;
    const float2* cv2 = (const float2*)sh_cv;
    const float2* ww2 = (const float2*)sh_w;
#pragma unroll
    for (int r = 0; r < 8; r++) {
        const int s = blockIdx.x * 64 + warp * 8 + r;
        const float pa = g_pa[cur][b * S + s];
        const __half2* ep2 = (const __half2*)(g_encproj_h + ((size_t)b * S + s) * TRG);
        float acc = 0.f;
#pragma unroll
        for (int p = 0; p < 8; p++) {
            int i2 = lane + p * 32;
            float2 e  = __half22float2(ep2[i2]);
            float2 hd = hd2[i2], cv = cv2[i2], ww = ww2[i2];
            acc = fmaf(tanh_ap(e.x + hd.x + pa * cv.x), ww.x, acc);
            acc = fmaf(tanh_ap(e.y + hd.y + pa * cv.y), ww.y, acc);
        }
        acc = warp_red_sum(acc);
        if (lane == 0) g_attn[b * S + s] = acc;
    }
}

// ---------------- K4: softmax + pa update + attn output + cenc fused ----------------
// grid 64 (b), block 1024
__global__ void k_softmax_cenc(float* __restrict__ out_attn_t, int cur) {
    __shared__ float red[32];
    __shared__ float satt[S];
    __shared__ float spart[3 * TRG];   // 3 partial (ax,ay) sets of 512
    const int b = blockIdx.x, tid = threadIdx.x;
    const int lane = tid & 31, warp = tid >> 5;
    const int nxt = cur ^ 1;

    // ---- softmax over S ----
    float v = g_attn[b * S + tid];
    float m = v;
#pragma unroll
    for (int o = 16; o; o >>= 1) m = fmaxf(m, __shfl_xor_sync(0xffffffffu, m, o));
    if (lane == 0) red[warp] = m;
    __syncthreads();
    if (warp == 0) {
        float mm = red[lane];
#pragma unroll
        for (int o = 16; o; o >>= 1) mm = fmaxf(mm, __shfl_xor_sync(0xffffffffu, mm, o));
        if (lane == 0) red[0] = mm;
    }
    __syncthreads();
    m = red[0];
    __syncthreads();
    float e = __expf(v - m);
    float sum = warp_red_sum(e);
    if (lane == 0) red[warp] = sum;
    __syncthreads();
    if (warp == 0) {
        float ss = red[lane];
#pragma unroll
        for (int o = 16; o; o >>= 1) ss += __shfl_xor_sync(0xffffffffu, ss, o);
        if (lane == 0) red[0] = ss;
    }
    __syncthreads();
    float a = e / red[0];
    satt[tid] = a;
    out_attn_t[(size_t)b * S + tid] = a;
    g_pa[nxt][b * S + tid] = g_pa[cur][b * S + tid] + a;
    __syncthreads();

    // ---- cenc: thread = (s-quarter, e-pair) ----
    const int eq = tid & 255;          // half2 column 0..255
    const int sq = tid >> 8;           // s quarter 0..3
    const __half2* e2 = (const __half2*)g_enc_h + ((size_t)b * S + sq * 256) * (ENC / 2) + eq;
    float ax = 0.f, ay = 0.f;
    const float* at = &satt[sq * 256];
#pragma unroll 4
    for (int s = 0; s < 256; s++) {
        float2 f = __half22float2(e2[(size_t)s * (ENC / 2)]);
        float w = at[s];
        ax = fmaf(w, f.x, ax);
        ay = fmaf(w, f.y, ay);
    }
    if (sq > 0) {
        spart[(sq - 1) * TRG + eq * 2]     = ax;
        spart[(sq - 1) * TRG + eq * 2 + 1] = ay;
    }
    __syncthreads();
    if (sq == 0) {
#pragma unroll
        for (int q = 0; q < 3; q++) {
            ax += spart[q * TRG + eq * 2];
            ay += spart[q * TRG + eq * 2 + 1];
        }
        g_cenc[b * TRG + eq * 2]     = ax;
        g_cenc[b * TRG + eq * 2 + 1] = ay;
    }
}

// ---------------- K5: ha GEMM (w_ao read once) + pgen ----------------
// grid 17: blocks 0..15 = ha tiles (32 j each), block 16 = pgen
__global__ void k_ha_pgen(const float* __restrict__ w_ao, const float* __restrict__ b_ao,
                          const float* __restrict__ input_, const float* __restrict__ w_pt,
                          const float* __restrict__ b_pt, float* __restrict__ out,
                          int cur, int t) {
    const int tid = threadIdx.x;
    const int nxt = cur ^ 1;
    if (blockIdx.x < 16) {
        __shared__ float As[16][68];
        __shared__ float Bs[16][36];
        const int j0 = blockIdx.x * 32;
        const int ty = tid >> 4, tx = tid & 15;
        float acc[4][2];
#pragma unroll
        for (int i = 0; i < 4; i++) { acc[i][0] = 0.f; acc[i][1] = 0.f; }

        for (int k0 = 0; k0 < 1024; k0 += 16) {
            __syncthreads();
            {
                int b = tid >> 2, c4 = (tid & 3) * 4;
                int k = k0 + c4;
                float4 av = (k < TRG) ? *(const float4*)&g_cenc[b * TRG + k]
                                      : *(const float4*)&g_h[nxt][b * TRG + k - TRG];
                As[c4 + 0][b] = av.x; As[c4 + 1][b] = av.y;
                As[c4 + 2][b] = av.z; As[c4 + 3][b] = av.w;
            }
            if (tid < 128) {
                int c = tid >> 2, c4 = (tid & 3) * 4;
                float4 bv = *(const float4*)&w_ao[(size_t)(j0 + c) * (ENC + TRG) + k0 + c4];
                Bs[c4 + 0][c] = bv.x; Bs[c4 + 1][c] = bv.y;
                Bs[c4 + 2][c] = bv.z; Bs[c4 + 3][c] = bv.w;
            }
            __syncthreads();
#pragma unroll
            for (int kk = 0; kk < 16; kk++) {
                float a[4], bb[2];
#pragma unroll
                for (int i = 0; i < 4; i++) a[i] = As[kk][ty + 16 * i];
                bb[0] = Bs[kk][tx]; bb[1] = Bs[kk][tx + 16];
#pragma unroll
                for (int i = 0; i < 4; i++) {
                    acc[i][0] = fmaf(a[i], bb[0], acc[i][0]);
                    acc[i][1] = fmaf(a[i], bb[1], acc[i][1]);
                }
            }
        }
#pragma unroll
        for (int i = 0; i < 4; i++) {
            int b = ty + 16 * i;
#pragma unroll
            for (int jj = 0; jj < 2; jj++) {
                int j = j0 + tx + 16 * jj;
                float r = acc[i][jj] + b_ao[j];
                g_ha[nxt][b * TRG + j] = r;
                out[OUT_OFF + ((size_t)b * T + t) * TRG + j] = r;
            }
        }
    } else {
        // pgen: 8 warps, each handles 8 b
        const int warp = tid >> 5, lane = tid & 31;
#pragma unroll
        for (int r = 0; r < 8; r++) {
            int b = warp * 8 + r;
            const float* xt = input_ + ((size_t)b * T + t) * IN;
            float acc = 0.f;
            for (int k = lane; k < IN; k += 32)  acc = fmaf(w_pt[k], xt[k], acc);
            for (int k = lane; k < TRG; k += 32) acc = fmaf(w_pt[IN + k], g_h[nxt][b * TRG + k], acc);
            for (int k = lane; k < TRG; k += 32) acc = fmaf(w_pt[IN + TRG + k], g_cenc[b * TRG + k], acc);
            acc = warp_red_sum(acc);
            if (lane == 0) out[PGEN_OFF + (size_t)b * T + t] = sigmoidf_(acc + b_pt[0]);
        }
    }
}

// ---------------- finalize ----------------
__global__ void k_final(float* __restrict__ out, const float* __restrict__ past_dehy) {
    int i = blockIdx.x * blockDim.x + threadIdx.x;
    if (i < B * TRG) {
        out[HT_OFF + i]  = g_h[0][i];
        out[CT_OFF + i]  = g_c[0][i];
        out[HAT_OFF + i] = g_ha[0][i];
        out[PDH_OFF + i] = past_dehy[i];
    }
    if (i < B * S) out[PAT_OFF + i] = g_pa[0][i];
    if (i == 0) out[LOSS_OFF] = 0.f;
}

// ---------------- launch ----------------
extern "C" void kernel_launch(void* const* d_in, const int* in_sizes, int n_in,
                              void* d_out, int out_size) {
    const float* input_    = (const float*)d_in[1];
    const float* h0        = (const float*)d_in[2];
    const float* c0        = (const float*)d_in[3];
    const float* h_attn    = (const float*)d_in[4];
    const float* enc       = (const float*)d_in[5];
    const float* past_attn = (const float*)d_in[6];
    const float* past_dehy = (const float*)d_in[7];
    const float* w_ih      = (const float*)d_in[8];
    const float* b_ih      = (const float*)d_in[9];
    const float* w_hh      = (const float*)d_in[10];
    const float* b_hh      = (const float*)d_in[11];
    const float* w_en      = (const float*)d_in[12];
    const float* b_en      = (const float*)d_in[13];
    const float* w_de      = (const float*)d_in[14];
    const float* w_cv      = (const float*)d_in[15];
    const float* w_warp    = (const float*)d_in[16];
    const float* w_ao      = (const float*)d_in[17];
    const float* b_ao      = (const float*)d_in[18];
    const float* w_pt      = (const float*)d_in[19];
    const float* b_pt      = (const float*)d_in[20];
    float* out = (float*)d_out;

    __half *p_enc_h, *p_wen_h, *p_input_h, *p_encproj_h, *p_wihx_h;
    float *p_xg;
    cudaGetSymbolAddress((void**)&p_enc_h, g_enc_h);
    cudaGetSymbolAddress((void**)&p_wen_h, g_wen_h);
    cudaGetSymbolAddress((void**)&p_input_h, g_input_h);
    cudaGetSymbolAddress((void**)&p_encproj_h, g_encproj_h);
    cudaGetSymbolAddress((void**)&p_wihx_h, g_wihx_h);
    cudaGetSymbolAddress((void**)&p_xg, g_xg);

    k_init<<<(B * S + 255) / 256, 256>>>(h0, c0, h_attn, past_attn);
    k_f2h<<<(B * S * ENC) / 1024, 256>>>(enc, p_enc_h);
    k_f2h<<<(512 * 512) / 1024, 256>>>(w_en, p_wen_h);
    k_f2h<<<(B * T * IN) / 1024, 256>>>(input_, p_input_h);
    k_wihx<<<G4, 64>>>(w_ih);

    k_mma<true><<<dim3(512 / 64, (B * S) / 128), 256>>>(p_enc_h, p_wen_h, b_en,
                                                        p_encproj_h, 512, 512);
    k_mma<false><<<dim3(G4 / 64, (B * T) / 128), 256>>>(p_input_h, p_wihx_h, nullptr,
                                                        p_xg, IN, G4);

    for (int t = 0; t < T; t++) {
        int cur = t & 1;
        k_gates_lstm<<<64, 256>>>(w_ih, w_hh, b_ih, b_hh, cur, t);
        k_hde<<<16, 256>>>(w_de, cur);
        k_attnee<<<dim3(16, B), 256>>>(w_cv, w_warp, cur);
        k_softmax_cenc<<<B, 1024>>>(out + ATTN_OFF + (size_t)t * B * S, cur);
        k_ha_pgen<<<17, 256>>>(w_ao, b_ao, input_, w_pt, b_pt, out, cur, t);
    }
    k_final<<<(B * S + 255) / 256, 256>>>(out, past_dehy);
}

// round 6
// speedup vs baseline: 2.4193x; 2.4193x over previous
#include <cuda_runtime.h>
#include <cuda_fp16.h>
#include <math.h>

// Problem constants
#define B   64
#define T   100
#define S   1024
#define IN  256
#define TRG 512
#define ENC 512
#define G4  2048   // 4*TRG

// Output layout offsets (floats)
#define OUT_OFF   0
#define HT_OFF    3276800
#define CT_OFF    3309568
#define HAT_OFF   3342336
#define ATTN_OFF  3375104
#define PAT_OFF   9928704
#define PGEN_OFF  9994240
#define PDH_OFF   10000640
#define LOSS_OFF  10033408

// ---------------- device state ----------------
__device__ __align__(16) __half  g_encproj_h[(size_t)B * S * TRG];   // 67 MB
__device__ __align__(16) __half  g_enc_h[(size_t)B * S * ENC];       // 67 MB
__device__ __align__(16) __half  g_wen_h[512 * 512];
__device__ __align__(16) __half  g_input_h[B * T * IN];
__device__ __align__(16) __half  g_wihx_h[G4 * IN];
__device__ __align__(16) __half  g_wr_h[(size_t)G4 * 1024];          // recurrent weights fp16, 4MB
__device__ __align__(16) __half  g_wde_h[TRG * TRG];                 // w_de fp16
__device__ __align__(16) __half  g_x_h[B * 1024];                    // [ha | h] fp16 image
__device__ __align__(16) float   g_xg[(size_t)B * T * G4];           // 52 MB
__device__ __align__(16) float g_h[B * TRG];
__device__ __align__(16) float g_c[B * TRG];
__device__ __align__(16) float g_ha[B * TRG];
__device__ __align__(16) float g_pa[B * S];
__device__ __align__(16) float g_gp4[4][B * G4];                     // gates split-K partials
__device__ __align__(16) float g_hde4[4][B * TRG];                   // hde split-K partials
__device__ __align__(16) float g_attn[B * S];
__device__ __align__(16) float g_cenc[B * TRG];

__device__ __forceinline__ float warp_red_sum(float v) {
#pragma unroll
    for (int o = 16; o; o >>= 1) v += __shfl_xor_sync(0xffffffffu, v, o);
    return v;
}
__device__ __forceinline__ float sigmoidf_(float x) { return 1.0f / (1.0f + expf(-x)); }
__device__ __forceinline__ float tanh_ap(float x) {
    float y; asm("tanh.approx.f32 %0, %1;" : "=f"(y) : "f"(x)); return y;
}
__device__ __forceinline__ unsigned smem_u32(const void* p) {
    return (unsigned)__cvta_generic_to_shared(p);
}

// ---------------- init ----------------
__global__ void k_init(const float* __restrict__ h0, const float* __restrict__ c0,
                       const float* __restrict__ h_attn, const float* __restrict__ past_attn) {
    int i = blockIdx.x * blockDim.x + threadIdx.x;
    if (i < B * TRG) {
        g_h[i] = h0[i]; g_c[i] = c0[i]; g_ha[i] = h_attn[i];
        int b = i >> 9, j = i & 511;
        g_x_h[b * 1024 + j]       = __float2half_rn(h_attn[i]);
        g_x_h[b * 1024 + 512 + j] = __float2half_rn(h0[i]);
    }
    if (i < B * S) g_pa[i] = past_attn[i];
}

// ---------------- generic f32 -> f16 (n multiple of 1024) ----------------
__global__ void k_f2h(const float* __restrict__ src, __half* __restrict__ dst) {
    size_t i = ((size_t)blockIdx.x * blockDim.x + threadIdx.x) * 4;
    float4 v = *(const float4*)&src[i];
    __half2* d = (__half2*)&dst[i];
    d[0] = __floats2half2_rn(v.x, v.y);
    d[1] = __floats2half2_rn(v.z, v.w);
}

// w_ih[:, 0:256] -> compact fp16 [2048][256]
__global__ void k_wihx(const float* __restrict__ w_ih) {
    int n = blockIdx.x;
    for (int c = threadIdx.x; c < IN; c += 64)
        g_wihx_h[n * IN + c] = __float2half_rn(w_ih[(size_t)n * (IN + TRG) + c]);
}

// Wr row n = [w_ih[n,256:768] | w_hh[n,:]] -> fp16 [2048][1024]
__global__ void k_wr(const float* __restrict__ w_ih, const float* __restrict__ w_hh) {
    int n = blockIdx.x;
    for (int k = threadIdx.x; k < 1024; k += 256) {
        float v = (k < TRG) ? w_ih[(size_t)n * (IN + TRG) + IN + k]
                            : w_hh[(size_t)n * TRG + k - TRG];
        g_wr_h[(size_t)n * 1024 + k] = __float2half_rn(v);
    }
}

// ---------------- fp16 tensor-core GEMM (setup: encproj, xg) ----------------
template<bool OUT16>
__global__ void k_mma(const __half* __restrict__ A, const __half* __restrict__ W,
                      const float* __restrict__ bias, void* __restrict__ Cout,
                      int K, int ldc) {
    __shared__ __align__(16) char smem_raw[128 * 68 * 4];
    __shared__ float sBias[64];
    __half (*sA)[72] = (__half(*)[72])smem_raw;
    __half (*sB)[72] = (__half(*)[72])(smem_raw + 18432);

    const int m0 = blockIdx.y * 128;
    const int n0 = blockIdx.x * 64;
    const int tid = threadIdx.x;
    const int lane = tid & 31;
    const int w = tid >> 5;
    const int wm = (w >> 1) * 32;
    const int wn = (w & 1) * 32;

    if (OUT16 && tid < 64) sBias[tid] = bias[n0 + tid];

    float c[2][4][4];
#pragma unroll
    for (int i = 0; i < 2; i++)
#pragma unroll
        for (int j = 0; j < 4; j++)
#pragma unroll
            for (int q = 0; q < 4; q++) c[i][j][q] = 0.f;

    const int lrow = lane & 15;
    const int lcol = (lane >> 4) * 8;

    for (int k0 = 0; k0 < K; k0 += 64) {
        __syncthreads();
        {
            int r = tid >> 3, cc = (tid & 7) * 8;
#pragma unroll
            for (int p = 0; p < 4; p++)
                *(float4*)&sA[r + p * 32][cc] =
                    *(const float4*)&A[(size_t)(m0 + r + p * 32) * K + k0 + cc];
#pragma unroll
            for (int p = 0; p < 2; p++)
                *(float4*)&sB[r + p * 32][cc] =
                    *(const float4*)&W[(size_t)(n0 + r + p * 32) * K + k0 + cc];
        }
        __syncthreads();
#pragma unroll
        for (int kk = 0; kk < 4; kk++) {
            unsigned a[2][4], bf[4][2];
#pragma unroll
            for (int mt = 0; mt < 2; mt++) {
                unsigned addr = smem_u32(&sA[wm + mt * 16 + lrow][kk * 16 + lcol]);
                asm volatile("ldmatrix.sync.aligned.m8n8.x4.shared.b16 {%0,%1,%2,%3}, [%4];"
                             : "=r"(a[mt][0]), "=r"(a[mt][1]), "=r"(a[mt][2]), "=r"(a[mt][3])
                             : "r"(addr));
            }
#pragma unroll
            for (int bp = 0; bp < 2; bp++) {
                unsigned r0, r1, r2, r3;
                unsigned addr = smem_u32(&sB[wn + bp * 16 + lrow][kk * 16 + lcol]);
                asm volatile("ldmatrix.sync.aligned.m8n8.x4.shared.b16 {%0,%1,%2,%3}, [%4];"
                             : "=r"(r0), "=r"(r1), "=r"(r2), "=r"(r3) : "r"(addr));
                bf[bp * 2 + 0][0] = r0; bf[bp * 2 + 0][1] = r2;
                bf[bp * 2 + 1][0] = r1; bf[bp * 2 + 1][1] = r3;
            }
#pragma unroll
            for (int mt = 0; mt < 2; mt++)
#pragma unroll
                for (int nf = 0; nf < 4; nf++) {
                    asm volatile(
                        "mma.sync.aligned.m16n8k16.row.col.f32.f16.f16.f32 "
                        "{%0,%1,%2,%3}, {%4,%5,%6,%7}, {%8,%9}, {%0,%1,%2,%3};"
                        : "+f"(c[mt][nf][0]), "+f"(c[mt][nf][1]),
                          "+f"(c[mt][nf][2]), "+f"(c[mt][nf][3])
                        : "r"(a[mt][0]), "r"(a[mt][1]), "r"(a[mt][2]), "r"(a[mt][3]),
                          "r"(bf[nf][0]), "r"(bf[nf][1]));
                }
        }
    }
    __syncthreads();
    float (*sO)[68] = (float(*)[68])smem_raw;
    {
        int g = lane >> 2, tq = lane & 3;
#pragma unroll
        for (int mt = 0; mt < 2; mt++)
#pragma unroll
            for (int nf = 0; nf < 4; nf++) {
                int r = wm + mt * 16 + g;
                int cc = wn + (nf >> 1) * 16 + (nf & 1) * 8 + tq * 2;
                sO[r][cc]     = c[mt][nf][0]; sO[r][cc + 1]     = c[mt][nf][1];
                sO[r + 8][cc] = c[mt][nf][2]; sO[r + 8][cc + 1] = c[mt][nf][3];
            }
    }
    __syncthreads();
#pragma unroll
    for (int p = 0; p < 4; p++) {
        int idx = p * 256 + tid;
        int r = idx >> 3, c8 = (idx & 7) * 8;
        if (OUT16) {
            __half* C = (__half*)Cout;
            __half2 h[4];
#pragma unroll
            for (int q = 0; q < 4; q++)
                h[q] = __floats2half2_rn(sO[r][c8 + 2 * q] + sBias[c8 + 2 * q],
                                         sO[r][c8 + 2 * q + 1] + sBias[c8 + 2 * q + 1]);
            *(float4*)&C[(size_t)(m0 + r) * ldc + n0 + c8] = *(float4*)h;
        } else {
            float* C = (float*)Cout;
            *(float4*)&C[(size_t)(m0 + r) * ldc + n0 + c8]     = *(float4*)&sO[r][c8];
            *(float4*)&C[(size_t)(m0 + r) * ldc + n0 + c8 + 4] = *(float4*)&sO[r][c8 + 4];
        }
    }
}

// ---------------- per-step TC GEMM: M=64, N-tile 64, split-K ----------------
// outP[split][64][ldo]; out fp32 partials. grid (N/64, nsplit), block 256.
__global__ void k_tc_gemm(const __half* __restrict__ A, int lda,
                          const __half* __restrict__ W, int ldw,
                          float* __restrict__ outP, int ldo, int kps) {
    __shared__ __align__(16) __half sA[64][72];
    __shared__ __align__(16) __half sB[64][72];
    const int n0 = blockIdx.x * 64;
    const int kbase = blockIdx.y * kps;
    float* out = outP + (size_t)blockIdx.y * 64 * ldo;
    const int tid = threadIdx.x;
    const int lane = tid & 31;
    const int w = tid >> 5;
    const int wm = (w >> 2) * 32;   // 2 M-warps
    const int wn = (w & 3) * 16;    // 4 N-warps

    float c[2][2][4];
#pragma unroll
    for (int i = 0; i < 2; i++)
#pragma unroll
        for (int j = 0; j < 2; j++)
#pragma unroll
            for (int q = 0; q < 4; q++) c[i][j][q] = 0.f;

    const int lrow = lane & 15;
    const int lcol = (lane >> 4) * 8;

    for (int k0 = kbase; k0 < kbase + kps; k0 += 64) {
        __syncthreads();
#pragma unroll
        for (int p = 0; p < 2; p++) {
            int idx = p * 256 + tid;
            int r = idx >> 3, c8 = (idx & 7) * 8;
            *(float4*)&sA[r][c8] = *(const float4*)&A[(size_t)r * lda + k0 + c8];
            *(float4*)&sB[r][c8] = *(const float4*)&W[(size_t)(n0 + r) * ldw + k0 + c8];
        }
        __syncthreads();
#pragma unroll
        for (int kk = 0; kk < 4; kk++) {
            unsigned a[2][4], bf[2][2];
#pragma unroll
            for (int mt = 0; mt < 2; mt++) {
                unsigned addr = smem_u32(&sA[wm + mt * 16 + lrow][kk * 16 + lcol]);
                asm volatile("ldmatrix.sync.aligned.m8n8.x4.shared.b16 {%0,%1,%2,%3}, [%4];"
                             : "=r"(a[mt][0]), "=r"(a[mt][1]), "=r"(a[mt][2]), "=r"(a[mt][3])
                             : "r"(addr));
            }
            {
                unsigned r0, r1, r2, r3;
                unsigned addr = smem_u32(&sB[wn + lrow][kk * 16 + lcol]);
                asm volatile("ldmatrix.sync.aligned.m8n8.x4.shared.b16 {%0,%1,%2,%3}, [%4];"
                             : "=r"(r0), "=r"(r1), "=r"(r2), "=r"(r3) : "r"(addr));
                bf[0][0] = r0; bf[0][1] = r2;
                bf[1][0] = r1; bf[1][1] = r3;
            }
#pragma unroll
            for (int mt = 0; mt < 2; mt++)
#pragma unroll
                for (int nf = 0; nf < 2; nf++) {
                    asm volatile(
                        "mma.sync.aligned.m16n8k16.row.col.f32.f16.f16.f32 "
                        "{%0,%1,%2,%3}, {%4,%5,%6,%7}, {%8,%9}, {%0,%1,%2,%3};"
                        : "+f"(c[mt][nf][0]), "+f"(c[mt][nf][1]),
                          "+f"(c[mt][nf][2]), "+f"(c[mt][nf][3])
                        : "r"(a[mt][0]), "r"(a[mt][1]), "r"(a[mt][2]), "r"(a[mt][3]),
                          "r"(bf[nf][0]), "r"(bf[nf][1]));
                }
        }
    }
    // direct fragment writeback of fp32 partials
    const int g = lane >> 2, tq = lane & 3;
#pragma unroll
    for (int mt = 0; mt < 2; mt++)
#pragma unroll
        for (int nf = 0; nf < 2; nf++) {
            int r = wm + mt * 16 + g;
            int cc = n0 + wn + nf * 8 + tq * 2;
            out[(size_t)r * ldo + cc]           = c[mt][nf][0];
            out[(size_t)r * ldo + cc + 1]       = c[mt][nf][1];
            out[(size_t)(r + 8) * ldo + cc]     = c[mt][nf][2];
            out[(size_t)(r + 8) * ldo + cc + 1] = c[mt][nf][3];
        }
}

// ---------------- K2: LSTM pointwise (sums 4 partials + xg) ----------------
// grid 128, block 256
__global__ void k_lstm(const float* __restrict__ b_ih, const float* __restrict__ b_hh, int t) {
    int idx = blockIdx.x * 256 + threadIdx.x;
    int b = idx >> 9, j = idx & 511;
    const float* xgp = g_xg + ((size_t)b * T + t) * G4;
    float gi = b_ih[j]           + b_hh[j]           + xgp[j];
    float gf = b_ih[TRG + j]     + b_hh[TRG + j]     + xgp[TRG + j];
    float gg = b_ih[2 * TRG + j] + b_hh[2 * TRG + j] + xgp[2 * TRG + j];
    float go = b_ih[3 * TRG + j] + b_hh[3 * TRG + j] + xgp[3 * TRG + j];
#pragma unroll
    for (int s = 0; s < 4; s++) {
        const float* gp = g_gp4[s] + b * G4;
        gi += gp[j]; gf += gp[TRG + j]; gg += gp[2 * TRG + j]; go += gp[3 * TRG + j];
    }
    float cn = sigmoidf_(gf) * g_c[idx] + sigmoidf_(gi) * tanhf(gg);
    float hn = sigmoidf_(go) * tanhf(cn);
    g_c[idx] = cn;
    g_h[idx] = hn;
    g_x_h[b * 1024 + 512 + j] = __float2half_rn(hn);
}

// ---------------- K3: attn logits; sums hde partials into smem ----------------
// grid (16, 64), block 256
__global__ void k_attnee(const float* __restrict__ cv_w, const float* __restrict__ warp_w) {
    __shared__ __align__(16) float sh_hde[TRG], sh_cv[TRG], sh_w[TRG];
    const int b = blockIdx.y, tid = threadIdx.x;
    for (int i = tid; i < TRG; i += 256) {
        sh_hde[i] = g_hde4[0][b * TRG + i] + g_hde4[1][b * TRG + i]
                  + g_hde4[2][b * TRG + i] + g_hde4[3][b * TRG + i];
        sh_cv[i]  = cv_w[i];
        sh_w[i]   = warp_w[i];
    }
    __syncthreads();
    const int warp = tid >> 5, lane = tid & 31;
    const float2* hd2 = (const float2*)sh_hde;
    const float2* cv2 = (const float2*)sh_cv;
    const float2* ww2 = (const float2*)sh_w;
#pragma unroll
    for (int r = 0; r < 8; r++) {
        const int s = blockIdx.x * 64 + warp * 8 + r;
        const float pa = g_pa[b * S + s];
        const __half2* ep2 = (const __half2*)(g_encproj_h + ((size_t)b * S + s) * TRG);
        float acc = 0.f;
#pragma unroll
        for (int p = 0; p < 8; p++) {
            int i2 = lane + p * 32;
            float2 e  = __half22float2(ep2[i2]);
            float2 hd = hd2[i2], cv = cv2[i2], ww = ww2[i2];
            acc = fmaf(tanh_ap(e.x + hd.x + pa * cv.x), ww.x, acc);
            acc = fmaf(tanh_ap(e.y + hd.y + pa * cv.y), ww.y, acc);
        }
        acc = warp_red_sum(acc);
        if (lane == 0) g_attn[b * S + s] = acc;
    }
}

// ---------------- K4: softmax + pa update + attn out + cenc fused ----------------
// grid 64 (b), block 1024
__global__ void k_softmax_cenc(float* __restrict__ out_attn_t) {
    __shared__ float red[32];
    __shared__ float satt[S];
    __shared__ float spart[3 * TRG];
    const int b = blockIdx.x, tid = threadIdx.x;
    const int lane = tid & 31, warp = tid >> 5;

    float v = g_attn[b * S + tid];
    float m = v;
#pragma unroll
    for (int o = 16; o; o >>= 1) m = fmaxf(m, __shfl_xor_sync(0xffffffffu, m, o));
    if (lane == 0) red[warp] = m;
    __syncthreads();
    if (warp == 0) {
        float mm = red[lane];
#pragma unroll
        for (int o = 16; o; o >>= 1) mm = fmaxf(mm, __shfl_xor_sync(0xffffffffu, mm, o));
        if (lane == 0) red[0] = mm;
    }
    __syncthreads();
    m = red[0];
    __syncthreads();
    float e = __expf(v - m);
    float sum = warp_red_sum(e);
    if (lane == 0) red[warp] = sum;
    __syncthreads();
    if (warp == 0) {
        float ss = red[lane];
#pragma unroll
        for (int o = 16; o; o >>= 1) ss += __shfl_xor_sync(0xffffffffu, ss, o);
        if (lane == 0) red[0] = ss;
    }
    __syncthreads();
    float a = e / red[0];
    satt[tid] = a;
    out_attn_t[(size_t)b * S + tid] = a;
    g_pa[b * S + tid] += a;
    __syncthreads();

    const int eq = tid & 255;
    const int sq = tid >> 8;
    const __half2* e2 = (const __half2*)g_enc_h + ((size_t)b * S + sq * 256) * (ENC / 2) + eq;
    float ax = 0.f, ay = 0.f;
    const float* at = &satt[sq * 256];
#pragma unroll 4
    for (int s = 0; s < 256; s++) {
        float2 f = __half22float2(e2[(size_t)s * (ENC / 2)]);
        float wv = at[s];
        ax = fmaf(wv, f.x, ax);
        ay = fmaf(wv, f.y, ay);
    }
    if (sq > 0) {
        spart[(sq - 1) * TRG + eq * 2]     = ax;
        spart[(sq - 1) * TRG + eq * 2 + 1] = ay;
    }
    __syncthreads();
    if (sq == 0) {
#pragma unroll
        for (int q = 0; q < 3; q++) {
            ax += spart[q * TRG + eq * 2];
            ay += spart[q * TRG + eq * 2 + 1];
        }
        g_cenc[b * TRG + eq * 2]     = ax;
        g_cenc[b * TRG + eq * 2 + 1] = ay;
    }
}

// ---------------- K5: ha GEMM (fp32, 2-D grid) + pgen ----------------
// grid 129: blocks 0..127 = (jt 0..15) x (bt 0..7); block 128 = pgen
__global__ void k_ha_pgen(const float* __restrict__ w_ao, const float* __restrict__ b_ao,
                          const float* __restrict__ input_, const float* __restrict__ w_pt,
                          const float* __restrict__ b_pt, float* __restrict__ out, int t) {
    __shared__ __align__(16) float sX[8][1024];
    const int tid = threadIdx.x;
    if (blockIdx.x < 128) {
        const int jt = blockIdx.x >> 3, bt = blockIdx.x & 7;
        const int j0 = jt * 32, b0 = bt * 8;
        // stage X = [cenc | h] for 8 b rows
        for (int i = tid; i < 8 * 1024; i += 256) {
            int bb = i >> 10, k = i & 1023;
            sX[bb][k] = (k < TRG) ? g_cenc[(b0 + bb) * TRG + k]
                                  : g_h[(b0 + bb) * TRG + k - TRG];
        }
        __syncthreads();
        const int warp = tid >> 5, lane = tid & 31;
#pragma unroll
        for (int jj = 0; jj < 4; jj++) {
            const int j = j0 + warp * 4 + jj;
            const float* wrow = w_ao + (size_t)j * 1024;
            float acc[8];
#pragma unroll
            for (int bb = 0; bb < 8; bb++) acc[bb] = 0.f;
#pragma unroll
            for (int i = 0; i < 8; i++) {
                int k = i * 128 + lane * 4;
                float4 wv = *(const float4*)&wrow[k];
#pragma unroll
                for (int bb = 0; bb < 8; bb++) {
                    float4 xv = *(const float4*)&sX[bb][k];
                    acc[bb] += wv.x * xv.x + wv.y * xv.y + wv.z * xv.z + wv.w * xv.w;
                }
            }
#pragma unroll
            for (int bb = 0; bb < 8; bb++) {
                float r = warp_red_sum(acc[bb]);
                if (lane == 0) {
                    r += b_ao[j];
                    int b = b0 + bb;
                    g_ha[b * TRG + j] = r;
                    g_x_h[b * 1024 + j] = __float2half_rn(r);
                    out[OUT_OFF + ((size_t)b * T + t) * TRG + j] = r;
                }
            }
        }
    } else {
        // pgen: 8 warps, each 8 b
        const int warp = tid >> 5, lane = tid & 31;
#pragma unroll
        for (int r = 0; r < 8; r++) {
            int b = warp * 8 + r;
            const float* xt = input_ + ((size_t)b * T + t) * IN;
            float acc = 0.f;
            for (int k = lane; k < IN; k += 32)  acc = fmaf(w_pt[k], xt[k], acc);
            for (int k = lane; k < TRG; k += 32) acc = fmaf(w_pt[IN + k], g_h[b * TRG + k], acc);
            for (int k = lane; k < TRG; k += 32) acc = fmaf(w_pt[IN + TRG + k], g_cenc[b * TRG + k], acc);
            acc = warp_red_sum(acc);
            if (lane == 0) out[PGEN_OFF + (size_t)b * T + t] = sigmoidf_(acc + b_pt[0]);
        }
    }
}

// ---------------- finalize ----------------
__global__ void k_final(float* __restrict__ out, const float* __restrict__ past_dehy) {
    int i = blockIdx.x * blockDim.x + threadIdx.x;
    if (i < B * TRG) {
        out[HT_OFF + i]  = g_h[i];
        out[CT_OFF + i]  = g_c[i];
        out[HAT_OFF + i] = g_ha[i];
        out[PDH_OFF + i] = past_dehy[i];
    }
    if (i < B * S) out[PAT_OFF + i] = g_pa[i];
    if (i == 0) out[LOSS_OFF] = 0.f;
}

// ---------------- launch ----------------
extern "C" void kernel_launch(void* const* d_in, const int* in_sizes, int n_in,
                              void* d_out, int out_size) {
    const float* input_    = (const float*)d_in[1];
    const float* h0        = (const float*)d_in[2];
    const float* c0        = (const float*)d_in[3];
    const float* h_attn    = (const float*)d_in[4];
    const float* enc       = (const float*)d_in[5];
    const float* past_attn = (const float*)d_in[6];
    const float* past_dehy = (const float*)d_in[7];
    const float* w_ih      = (const float*)d_in[8];
    const float* b_ih      = (const float*)d_in[9];
    const float* w_hh      = (const float*)d_in[10];
    const float* b_hh      = (const float*)d_in[11];
    const float* w_en      = (const float*)d_in[12];
    const float* b_en      = (const float*)d_in[13];
    const float* w_de      = (const float*)d_in[14];
    const float* w_cv      = (const float*)d_in[15];
    const float* w_warp    = (const float*)d_in[16];
    const float* w_ao      = (const float*)d_in[17];
    const float* b_ao      = (const float*)d_in[18];
    const float* w_pt      = (const float*)d_in[19];
    const float* b_pt      = (const float*)d_in[20];
    float* out = (float*)d_out;

    __half *p_enc_h, *p_wen_h, *p_input_h, *p_encproj_h, *p_wihx_h, *p_wr_h, *p_wde_h, *p_x_h;
    float *p_xg, *p_gp4, *p_hde4;
    cudaGetSymbolAddress((void**)&p_enc_h, g_enc_h);
    cudaGetSymbolAddress((void**)&p_wen_h, g_wen_h);
    cudaGetSymbolAddress((void**)&p_input_h, g_input_h);
    cudaGetSymbolAddress((void**)&p_encproj_h, g_encproj_h);
    cudaGetSymbolAddress((void**)&p_wihx_h, g_wihx_h);
    cudaGetSymbolAddress((void**)&p_wr_h, g_wr_h);
    cudaGetSymbolAddress((void**)&p_wde_h, g_wde_h);
    cudaGetSymbolAddress((void**)&p_x_h, g_x_h);
    cudaGetSymbolAddress((void**)&p_xg, g_xg);
    cudaGetSymbolAddress((void**)&p_gp4, g_gp4);
    cudaGetSymbolAddress((void**)&p_hde4, g_hde4);

    k_init<<<(B * S + 255) / 256, 256>>>(h0, c0, h_attn, past_attn);
    k_f2h<<<(B * S * ENC) / 1024, 256>>>(enc, p_enc_h);
    k_f2h<<<(512 * 512) / 1024, 256>>>(w_en, p_wen_h);
    k_f2h<<<(B * T * IN) / 1024, 256>>>(input_, p_input_h);
    k_f2h<<<(TRG * TRG) / 1024, 256>>>(w_de, p_wde_h);
    k_wihx<<<G4, 64>>>(w_ih);
    k_wr<<<G4, 256>>>(w_ih, w_hh);

    k_mma<true><<<dim3(512 / 64, (B * S) / 128), 256>>>(p_enc_h, p_wen_h, b_en,
                                                        p_encproj_h, 512, 512);
    k_mma<false><<<dim3(G4 / 64, (B * T) / 128), 256>>>(p_input_h, p_wihx_h, nullptr,
                                                        p_xg, IN, G4);

    for (int t = 0; t < T; t++) {
        // gates: [64,2048] = X[64,1024] @ Wr^T, split-K 4x256
        k_tc_gemm<<<dim3(32, 4), 256>>>(p_x_h, 1024, p_wr_h, 1024, p_gp4, G4, 256);
        k_lstm<<<128, 256>>>(b_ih, b_hh, t);
        // hde: [64,512] = h[64,512] @ w_de^T, split-K 4x128
        k_tc_gemm<<<dim3(8, 4), 256>>>(p_x_h + 512, 1024, p_wde_h, 512, p_hde4, TRG, 128);
        k_attnee<<<dim3(16, B), 256>>>(w_cv, w_warp);
        k_softmax_cenc<<<B, 1024>>>(out + ATTN_OFF + (size_t)t * B * S);
        k_ha_pgen<<<129, 256>>>(w_ao, b_ao, input_, w_pt, b_pt, out, t);
    }
    k_final<<<(B * S + 255) / 256, 256>>>(out, past_dehy);
}